// round 6
// baseline (speedup 1.0000x reference)
#include <cuda_runtime.h>

typedef unsigned int U32;

__device__ __forceinline__ U32 tf32r(float x) {
    U32 r;
    asm("cvt.rna.tf32.f32 %0, %1;" : "=r"(r) : "f"(x));
    return r;
}
__device__ __forceinline__ void mma_tf32(
    float& c0, float& c1, float& c2, float& c3,
    U32 a0, U32 a1, U32 a2, U32 a3, U32 b0, U32 b1)
{
    asm volatile(
        "mma.sync.aligned.m16n8k8.row.col.f32.tf32.tf32.f32 "
        "{%0,%1,%2,%3}, {%4,%5,%6,%7}, {%8,%9}, {%0,%1,%2,%3};"
        : "+f"(c0), "+f"(c1), "+f"(c2), "+f"(c3)
        : "r"(a0), "r"(a1), "r"(a2), "r"(a3), "r"(b0), "r"(b1));
}
// split fp32 -> {hi,lo,hi,lo} tf32 pair (exact: a = hi + lo to ~2^-24)
__device__ __forceinline__ float4 split4(float a, float b) {
    U32 h0 = tf32r(a); U32 l0 = tf32r(a - __uint_as_float(h0));
    U32 h1 = tf32r(b); U32 l1 = tf32r(b - __uint_as_float(h1));
    return make_float4(__uint_as_float(h0), __uint_as_float(l0),
                       __uint_as_float(h1), __uint_as_float(l1));
}

// Scratch (cudaMalloc forbidden; __device__ globals allowed)
__device__ float g_s [1024 * 256];
__device__ float g_t [1024 * 256];
__device__ float g_s2[1024 * 256];
__device__ float g_t2[1024 * 256];

// ---------------------------------------------------------------------------
// gemm_tc: C[m][n] = act( sum_k A[m*K+k] * B[n*ldb+k] + bias[n] )
// Split-tf32 tensor-core GEMM, fp32-accurate (hi*hi + hi*lo + lo*hi).
// v2: hi/lo split computed ONCE per element at staging, stored as float2
// {hi,lo} in smem -> inner loop is pure LDS.64 + MMA (no ALU).
// CTA 32m x 32n, 64 threads (2 warps, warp = 16m x 32n). K-chunk 32,
// double buffered with register prefetch. 512 CTAs.
// Row stride 36 float2: fragment LDS.64 bank index (4g+tg) mod 16 ->
// conflict-free per 16-lane phase.
// ---------------------------------------------------------------------------
#define ST2 36

__global__ __launch_bounds__(64) void gemm_tc(
    const float* __restrict__ A0, const float* __restrict__ A1,
    const float* __restrict__ B0, const float* __restrict__ B1,
    const float* __restrict__ bias0, const float* __restrict__ bias1,
    float* __restrict__ C0, float* __restrict__ C1,
    int K, int ldb, int N, int relu)
{
    const float* A    = blockIdx.z ? A1 : A0;
    const float* B    = blockIdx.z ? B1 : B0;
    const float* bias = blockIdx.z ? bias1 : bias0;
    float*       C    = blockIdx.z ? C1 : C0;

    const int m0 = blockIdx.y * 32;
    const int n0 = blockIdx.x * 32;

    __shared__ __align__(16) float2 As[2][32][ST2];   // [m][k] {hi,lo}
    __shared__ __align__(16) float2 Bs[2][32][ST2];   // [n][k] {hi,lo}

    const int tid  = threadIdx.x;
    const int w    = tid >> 5;
    const int lane = tid & 31;
    const int g    = lane >> 2;   // 0..7
    const int tg   = lane & 3;    // 0..3
    const int r0   = w * 16 + g;

    // loader: row = tid>>1 (0..31), k-base = (tid&1)*16 (16 k's per thread)
    const int lrow = tid >> 1;
    const int lk   = (tid & 1) * 16;

    const float* Aptr = A + (size_t)(m0 + lrow) * K   + lk;
    const float* Bptr = B + (size_t)(n0 + lrow) * ldb + lk;

    float acc[4][4];
#pragma unroll
    for (int nt = 0; nt < 4; nt++)
#pragma unroll
        for (int c = 0; c < 4; c++) acc[nt][c] = 0.f;

    const int KC = K / 32;

    float4 pa[4], pb[4];
#pragma unroll
    for (int f = 0; f < 4; f++) {
        pa[f] = *(const float4*)(Aptr + f * 4);
        pb[f] = *(const float4*)(Bptr + f * 4);
    }
    {   // stage chunk 0
#pragma unroll
        for (int f = 0; f < 4; f++) {
            *(float4*)&As[0][lrow][lk + f * 4]     = split4(pa[f].x, pa[f].y);
            *(float4*)&As[0][lrow][lk + f * 4 + 2] = split4(pa[f].z, pa[f].w);
            *(float4*)&Bs[0][lrow][lk + f * 4]     = split4(pb[f].x, pb[f].y);
            *(float4*)&Bs[0][lrow][lk + f * 4 + 2] = split4(pb[f].z, pb[f].w);
        }
    }
    __syncthreads();

    for (int kc = 0; kc < KC; kc++) {
        const int cur = kc & 1;
        if (kc + 1 < KC) {
            const int koff = (kc + 1) * 32;
#pragma unroll
            for (int f = 0; f < 4; f++) {
                pa[f] = *(const float4*)(Aptr + koff + f * 4);
                pb[f] = *(const float4*)(Bptr + koff + f * 4);
            }
        }
#pragma unroll
        for (int ks = 0; ks < 4; ks++) {
            const int k0 = ks * 8;
            float2 a00 = As[cur][r0    ][k0 + tg];
            float2 a10 = As[cur][r0 + 8][k0 + tg];
            float2 a01 = As[cur][r0    ][k0 + tg + 4];
            float2 a11 = As[cur][r0 + 8][k0 + tg + 4];
#pragma unroll
            for (int nt = 0; nt < 4; nt++) {
                float2 bv0 = Bs[cur][nt * 8 + g][k0 + tg];
                float2 bv1 = Bs[cur][nt * 8 + g][k0 + tg + 4];
                U32 bh0 = __float_as_uint(bv0.x), bh1 = __float_as_uint(bv1.x);
                U32 bl0 = __float_as_uint(bv0.y), bl1 = __float_as_uint(bv1.y);
                U32 ah0 = __float_as_uint(a00.x), ah1 = __float_as_uint(a10.x);
                U32 ah2 = __float_as_uint(a01.x), ah3 = __float_as_uint(a11.x);
                mma_tf32(acc[nt][0], acc[nt][1], acc[nt][2], acc[nt][3],
                         ah0, ah1, ah2, ah3, bh0, bh1);
                mma_tf32(acc[nt][0], acc[nt][1], acc[nt][2], acc[nt][3],
                         ah0, ah1, ah2, ah3, bl0, bl1);
                mma_tf32(acc[nt][0], acc[nt][1], acc[nt][2], acc[nt][3],
                         __float_as_uint(a00.y), __float_as_uint(a10.y),
                         __float_as_uint(a01.y), __float_as_uint(a11.y),
                         bh0, bh1);
            }
        }
        if (kc + 1 < KC) {
            const int nxt = cur ^ 1;
#pragma unroll
            for (int f = 0; f < 4; f++) {
                *(float4*)&As[nxt][lrow][lk + f * 4]     = split4(pa[f].x, pa[f].y);
                *(float4*)&As[nxt][lrow][lk + f * 4 + 2] = split4(pa[f].z, pa[f].w);
                *(float4*)&Bs[nxt][lrow][lk + f * 4]     = split4(pb[f].x, pb[f].y);
                *(float4*)&Bs[nxt][lrow][lk + f * 4 + 2] = split4(pb[f].z, pb[f].w);
            }
        }
        __syncthreads();
    }

    // epilogue: c0:(g,2tg) c1:(g,2tg+1) c2:(g+8,2tg) c3:(g+8,2tg+1)
#pragma unroll
    for (int nt = 0; nt < 4; nt++) {
        const int col = n0 + nt * 8 + tg * 2;
        float b0 = 0.f, b1 = 0.f;
        if (bias) { b0 = bias[col]; b1 = bias[col + 1]; }
        float2 v0 = make_float2(acc[nt][0] + b0, acc[nt][1] + b1);
        float2 v1 = make_float2(acc[nt][2] + b0, acc[nt][3] + b1);
        if (relu) {
            v0.x = fmaxf(v0.x, 0.f); v0.y = fmaxf(v0.y, 0.f);
            v1.x = fmaxf(v1.x, 0.f); v1.y = fmaxf(v1.y, 0.f);
        }
        *(float2*)(C + (size_t)(m0 + r0)     * N + col) = v0;
        *(float2*)(C + (size_t)(m0 + r0 + 8) * N + col) = v1;
    }
}

// ---------------------------------------------------------------------------
// pair_mma: out[b,i,n,j] = sum_h relu(s2[b,i,h] + t2[b,j,h]) * fc3[n,h]
// via tf32 mma.sync.m16n8k8; pair fragments built in registers, never
// materialized. v2: smem h-layout permuted within each 8-group so that
// (h, h+4) are adjacent -> every fragment load is a single LDS.64.
// Row stride 132 float2 -> (4g+tg) mod 16 conflict-free per phase;
// s2 loads are warp-broadcast.
// perm: h = base8 + r  ->  pos = base8 + (r&3)*2 + (r>>2)
// ---------------------------------------------------------------------------
#define PROW 264                 // floats per row (132 float2)
#define PROW2 132
#define SM_T2F 0
#define SM_WF  (32 * PROW)
#define SM_SF  (64 * PROW)
#define PAIR_SMEM (80 * PROW * 4)

__global__ __launch_bounds__(256, 2) void pair_mma(
    const float* __restrict__ s2, const float* __restrict__ t2,
    const float* __restrict__ fc3, float* __restrict__ out)
{
    extern __shared__ float sm[];
    const int jt = blockIdx.x;   // 0..7   (j tile of 32)
    const int ig = blockIdx.y;   // 0..15  (i group of 16)
    const int b  = blockIdx.z;   // 0..3

    const int tid  = threadIdx.x;
    const int w    = tid >> 5;    // 0..7
    const int lane = tid & 31;
    const int g    = lane >> 2;   // 0..7
    const int tg   = lane & 3;    // 0..3
    const int wj   = w & 1;       // j half
    const int wi   = w >> 1;      // i quarter (0..3)

    // ---- stage tiles (permuted h layout) ----
    {   // t2 tile: 32 rows x 256 h
        const float* t2g = t2 + (size_t)(b * 256 + jt * 32) * 256;
#pragma unroll
        for (int r = 0; r < 8; r++) {
            int q   = tid + r * 256;        // 0..2047
            int row = q >> 6;               // 0..31
            int c4  = (q & 63) * 4;         // multiple of 4
            float4 v = *(const float4*)(t2g + row * 256 + c4);
            int base = c4 & ~7;
            int odd  = (c4 >> 2) & 1;
            float* d = sm + SM_T2F + row * PROW + base + odd;
            d[0] = v.x; d[2] = v.y; d[4] = v.z; d[6] = v.w;
        }
    }
    // fc3 -> tf32 bits, zero-padded to n=32, permuted
    for (int q = tid; q < 32 * 256; q += 256) {
        int n = q >> 8;
        int h = q & 255;
        float v = (n < 25) ? fc3[n * 256 + h] : 0.f;
        int pos = (h & ~7) + ((h & 3) * 2) + ((h >> 2) & 1);
        sm[SM_WF + n * PROW + pos] = __uint_as_float(tf32r(v));
    }
    {   // s2 rows for this i-group (16 rows), permuted
        const float* s2g = s2 + (size_t)(b * 256 + ig * 16) * 256;
        for (int q = tid; q < 16 * 256; q += 256) {
            int row = q >> 8;
            int h = q & 255;
            int pos = (h & ~7) + ((h & 3) * 2) + ((h >> 2) & 1);
            sm[SM_SF + row * PROW + pos] = s2g[row * 256 + h];
        }
    }
    __syncthreads();

    const float2* tA2 = (const float2*)sm + (size_t)(wj * 16 + g) * PROW2 + tg;
    const float2* tW2 = (const float2*)sm + (SM_WF / 2) + (size_t)g * PROW2 + tg;
    const float2* tS2 = (const float2*)sm + (SM_SF / 2) + (size_t)(wi * 4) * PROW2 + tg;

    float acc[4][4][4];   // [i][nt][c]
#pragma unroll
    for (int i = 0; i < 4; i++)
#pragma unroll
        for (int nt = 0; nt < 4; nt++)
#pragma unroll
            for (int c = 0; c < 4; c++) acc[i][nt][c] = 0.f;

#pragma unroll 4
    for (int ks = 0; ks < 32; ks++) {
        const int o = ks * 4;
        // t fragments (j rows g, g+8): one LDS.64 each -> (h k0+tg, h k0+tg+4)
        float2 u0 = tA2[o];
        float2 u1 = tA2[o + 8 * PROW2];
        // W fragments
        float2 wv[4];
#pragma unroll
        for (int nt = 0; nt < 4; nt++) wv[nt] = tW2[o + nt * 8 * PROW2];
#pragma unroll
        for (int i = 0; i < 4; i++) {
            float2 sv = tS2[o + i * PROW2];          // broadcast
            U32 a0 = tf32r(fmaxf(u0.x + sv.x, 0.f));
            U32 a1 = tf32r(fmaxf(u1.x + sv.x, 0.f));
            U32 a2 = tf32r(fmaxf(u0.y + sv.y, 0.f));
            U32 a3 = tf32r(fmaxf(u1.y + sv.y, 0.f));
#pragma unroll
            for (int nt = 0; nt < 4; nt++) {
                mma_tf32(acc[i][nt][0], acc[i][nt][1], acc[i][nt][2], acc[i][nt][3],
                         a0, a1, a2, a3,
                         __float_as_uint(wv[nt].x), __float_as_uint(wv[nt].y));
            }
        }
    }

    // store: D rows = j, cols = n
    const int jg = jt * 32 + wj * 16 + g;
#pragma unroll
    for (int i = 0; i < 4; i++) {
        const int ii = ig * 16 + wi * 4 + i;
        float* obase = out + ((size_t)(b * 256 + ii) * 25) * 256 + jg;
#pragma unroll
        for (int nt = 0; nt < 4; nt++) {
            int n0 = nt * 8 + tg * 2;
            if (n0 < 25) {
                obase[(size_t)n0 * 256]     = acc[i][nt][0];
                obase[(size_t)n0 * 256 + 8] = acc[i][nt][2];
            }
            if (n0 + 1 < 25) {
                obase[(size_t)(n0 + 1) * 256]     = acc[i][nt][1];
                obase[(size_t)(n0 + 1) * 256 + 8] = acc[i][nt][3];
            }
        }
    }
}

// ---------------------------------------------------------------------------
// Inputs (metadata order):
// 0 input_tensor [4,256,768]  1 s_fc_w [256,768]  2 s_fc_b [256]
// 3 t_fc_w [256,768]          4 t_fc_b [256]      5 fc2_w [256,512]
// 6 fc2_b [256]               7 fc3_w [25,256]
// Output: float32 [4,256,25,256]
// ---------------------------------------------------------------------------
extern "C" void kernel_launch(void* const* d_in, const int* in_sizes, int n_in,
                              void* d_out, int out_size)
{
    const float* X  = (const float*)d_in[0];
    const float* sw = (const float*)d_in[1];
    const float* sb = (const float*)d_in[2];
    const float* tw = (const float*)d_in[3];
    const float* tb = (const float*)d_in[4];
    const float* w2 = (const float*)d_in[5];
    const float* b2 = (const float*)d_in[6];
    const float* w3 = (const float*)d_in[7];
    float* out = (float*)d_out;

    float *gs, *gt, *gs2, *gt2;
    cudaGetSymbolAddress((void**)&gs,  g_s);
    cudaGetSymbolAddress((void**)&gt,  g_t);
    cudaGetSymbolAddress((void**)&gs2, g_s2);
    cudaGetSymbolAddress((void**)&gt2, g_t2);

    cudaFuncSetAttribute(pair_mma, cudaFuncAttributeMaxDynamicSharedMemorySize,
                         PAIR_SMEM);

    dim3 blk(64);
    dim3 g1(256 / 32, 1024 / 32, 2);   // 8 x 32 x 2 = 512 CTAs
    // s = relu(X @ s_fc_w^T + s_fc_b), t = relu(X @ t_fc_w^T + t_fc_b)
    gemm_tc<<<g1, blk>>>(X, X, sw, tw, sb, tb, gs, gt, 768, 768, 256, 1);
    // s2 = s @ w_s^T ; t2 = t @ w_t^T + fc2_b
    gemm_tc<<<g1, blk>>>(gs, gt, w2, w2 + 256, nullptr, b2, gs2, gt2, 256, 512, 256, 0);

    dim3 g3(8, 16, 4);                 // 512 CTAs, 256 threads
    pair_mma<<<g3, dim3(256), PAIR_SMEM>>>(gs2, gt2, w3, out);
}

// round 7
// speedup vs baseline: 1.0731x; 1.0731x over previous
#include <cuda_runtime.h>
#include <cuda_bf16.h>

typedef unsigned int U32;

__device__ __forceinline__ U32 tf32r(float x) {
    U32 r;
    asm("cvt.rna.tf32.f32 %0, %1;" : "=r"(r) : "f"(x));
    return r;
}
__device__ __forceinline__ void mma_tf32(
    float& c0, float& c1, float& c2, float& c3,
    U32 a0, U32 a1, U32 a2, U32 a3, U32 b0, U32 b1)
{
    asm volatile(
        "mma.sync.aligned.m16n8k8.row.col.f32.tf32.tf32.f32 "
        "{%0,%1,%2,%3}, {%4,%5,%6,%7}, {%8,%9}, {%0,%1,%2,%3};"
        : "+f"(c0), "+f"(c1), "+f"(c2), "+f"(c3)
        : "r"(a0), "r"(a1), "r"(a2), "r"(a3), "r"(b0), "r"(b1));
}
__device__ __forceinline__ void mma_bf16(
    float& c0, float& c1, float& c2, float& c3,
    U32 a0, U32 a1, U32 a2, U32 a3, U32 b0, U32 b1)
{
    asm volatile(
        "mma.sync.aligned.m16n8k16.row.col.f32.bf16.bf16.f32 "
        "{%0,%1,%2,%3}, {%4,%5,%6,%7}, {%8,%9}, {%0,%1,%2,%3};"
        : "+f"(c0), "+f"(c1), "+f"(c2), "+f"(c3)
        : "r"(a0), "r"(a1), "r"(a2), "r"(a3), "r"(b0), "r"(b1));
}
__device__ __forceinline__ void cp16(U32 dst, const void* src) {
    asm volatile("cp.async.ca.shared.global [%0], [%1], 16;" :: "r"(dst), "l"(src));
}
__device__ __forceinline__ void cp_commit() { asm volatile("cp.async.commit_group;"); }
__device__ __forceinline__ void cp_wait1()  { asm volatile("cp.async.wait_group 1;"); }
__device__ __forceinline__ void cp_wait0()  { asm volatile("cp.async.wait_group 0;"); }

// bf16 hi/lo split helpers. a = hi + lo + r,  |r| <= 2^-18 |a|
__device__ __forceinline__ void bsplit(float v, unsigned short& hs, unsigned short& ls) {
    __nv_bfloat16 h = __float2bfloat16_rn(v);
    float hf = __bfloat162float(h);
    __nv_bfloat16 l = __float2bfloat16_rn(v - hf);
    hs = __bfloat16_as_ushort(h);
    ls = __bfloat16_as_ushort(l);
}
// A-side packed word: {hi (low half), lo (high half)}
__device__ __forceinline__ U32 packA(float v) {
    unsigned short hs, ls; bsplit(v, hs, ls);
    return (U32)hs | ((U32)ls << 16);
}
// permute k within its 8-group so fragment LDS.64 gets (k, k+4) adjacent
__device__ __forceinline__ int permk(int k) {
    return (k & ~7) | ((k & 3) << 1) | ((k >> 2) & 1);
}

// Scratch (cudaMalloc forbidden; __device__ globals allowed)
__device__ U32   g_xp [1024 * 768];               // X packed-split, k-permuted
__device__ U32   g_swh[256 * 768], g_swl[256 * 768];
__device__ U32   g_twh[256 * 768], g_twl[256 * 768];
__device__ U32   g_w2h[256 * 512], g_w2l[256 * 512];
__device__ U32   g_s  [1024 * 256];               // stage1 out, packed-split, permuted
__device__ U32   g_t  [1024 * 256];
__device__ float g_s2 [1024 * 256];               // stage2 out, plain fp32
__device__ float g_t2 [1024 * 256];

// ---------------------------------------------------------------------------
// prep: one-time split of X and all weights into packed/permuted form.
//   A-type (X):     word = {hi, lo}
//   B-type (W):     hh word = {hi, hi};  l0 word = {lo, +0}
// ---------------------------------------------------------------------------
#define NX  (1024 * 768)
#define NW  (256 * 768)
#define NW2 (256 * 512)

__global__ void prep(const float* __restrict__ X,
                     const float* __restrict__ sw, const float* __restrict__ tw,
                     const float* __restrict__ w2)
{
    int i = blockIdx.x * blockDim.x + threadIdx.x;
    if (i < NX) {
        int row = i / 768, k = i % 768;
        g_xp[row * 768 + permk(k)] = packA(X[i]);
    }
    if (i < NW) {
        int row = i / 768, k = i % 768;
        int o = row * 768 + permk(k);
        unsigned short hs, ls;
        bsplit(sw[i], hs, ls);
        g_swh[o] = (U32)hs | ((U32)hs << 16);
        g_swl[o] = (U32)ls;
        bsplit(tw[i], hs, ls);
        g_twh[o] = (U32)hs | ((U32)hs << 16);
        g_twl[o] = (U32)ls;
    }
    if (i < NW2) {
        int row = i / 512, k = i % 512;
        int o = row * 512 + permk(k);
        unsigned short hs, ls;
        bsplit(w2[i], hs, ls);
        g_w2h[o] = (U32)hs | ((U32)hs << 16);
        g_w2l[o] = (U32)ls;
    }
}

// ---------------------------------------------------------------------------
// gemm_bf: C[m][n] = act( sum_k A[m][k]*B[n][k] + bias[n] ), fp32-accurate
// via packed bf16-split: D += A_pack x Bhh  +  A_pack x Bl0 (m16n8k16).
// Inner loop is pure LDS.64 + MMA (zero ALU). CTA 32m x 16n, 64 threads
// (2 warps stacked on m). K-chunk 32, cp.async double buffer. 1024 CTAs.
// smem row stride 40 words -> conflict-free fragment loads.
// packOut=1: epilogue writes packed-split permuted U32 (feeds next gemm).
// ---------------------------------------------------------------------------
#define SKW 40

__global__ __launch_bounds__(64) void gemm_bf(
    const U32* __restrict__ A0,  const U32* __restrict__ A1,
    const U32* __restrict__ Bh0, const U32* __restrict__ Bh1,
    const U32* __restrict__ Bl0, const U32* __restrict__ Bl1,
    const float* __restrict__ bias0, const float* __restrict__ bias1,
    void* C0, void* C1,
    int K, int ldb, int N, int relu, int packOut)
{
    const U32* A     = blockIdx.z ? A1 : A0;
    const U32* Bhp   = blockIdx.z ? Bh1 : Bh0;
    const U32* Blp   = blockIdx.z ? Bl1 : Bl0;
    const float* bias = blockIdx.z ? bias1 : bias0;
    void* C          = blockIdx.z ? C1 : C0;

    const int m0 = blockIdx.y * 32;
    const int n0 = blockIdx.x * 16;

    __shared__ __align__(16) U32 As[2][32][SKW];
    __shared__ __align__(16) U32 Bh[2][16][SKW];
    __shared__ __align__(16) U32 Bl[2][16][SKW];

    const int tid  = threadIdx.x;
    const int w    = tid >> 5;
    const int lane = tid & 31;
    const int g    = lane >> 2;   // 0..7
    const int tg   = lane & 3;    // 0..3
    const int r0   = w * 16 + g;

    const U32 asB = (U32)__cvta_generic_to_shared(&As[0][0][0]);
    const U32 bhB = (U32)__cvta_generic_to_shared(&Bh[0][0][0]);
    const U32 blB = (U32)__cvta_generic_to_shared(&Bl[0][0][0]);
    const U32 bufA = 32 * SKW * 4;
    const U32 bufB = 16 * SKW * 4;

    // A loader: row = tid>>1, word base = (tid&1)*16, 4 cp16
    const int la_row = tid >> 1;
    const int la_k   = (tid & 1) * 16;
    // B loader: row = tid>>2, word base = (tid&3)*8, 2 cp16 per variant
    const int lb_row = tid >> 2;
    const int lb_k   = (tid & 3) * 8;

    const U32* Aptr  = A   + (size_t)(m0 + la_row) * K   + la_k;
    const U32* Bhptr = Bhp + (size_t)(n0 + lb_row) * ldb + lb_k;
    const U32* Blptr = Blp + (size_t)(n0 + lb_row) * ldb + lb_k;

    const int KC = K / 32;

    float acc[2][4];
#pragma unroll
    for (int nt = 0; nt < 2; nt++)
#pragma unroll
        for (int c = 0; c < 4; c++) acc[nt][c] = 0.f;

    {   // stage chunk 0
#pragma unroll
        for (int c = 0; c < 4; c++)
            cp16(asB + (la_row * SKW + la_k + c * 4) * 4, Aptr + c * 4);
#pragma unroll
        for (int c = 0; c < 2; c++) {
            cp16(bhB + (lb_row * SKW + lb_k + c * 4) * 4, Bhptr + c * 4);
            cp16(blB + (lb_row * SKW + lb_k + c * 4) * 4, Blptr + c * 4);
        }
        cp_commit();
    }

    for (int kc = 0; kc < KC; kc++) {
        const int cur = kc & 1;
        if (kc + 1 < KC) {
            const int nxt = cur ^ 1;
            const int ko = (kc + 1) * 32;
#pragma unroll
            for (int c = 0; c < 4; c++)
                cp16(asB + nxt * bufA + (la_row * SKW + la_k + c * 4) * 4,
                     Aptr + ko + c * 4);
#pragma unroll
            for (int c = 0; c < 2; c++) {
                cp16(bhB + nxt * bufB + (lb_row * SKW + lb_k + c * 4) * 4,
                     Bhptr + ko + c * 4);
                cp16(blB + nxt * bufB + (lb_row * SKW + lb_k + c * 4) * 4,
                     Blptr + ko + c * 4);
            }
            cp_commit();
            cp_wait1();
        } else {
            cp_wait0();
        }
        __syncthreads();

#pragma unroll
        for (int ks = 0; ks < 4; ks++) {
            const int o = ks * 8 + 2 * tg;
            uint2 aA = *(const uint2*)&As[cur][r0    ][o];   // a0, a2
            uint2 aB = *(const uint2*)&As[cur][r0 + 8][o];   // a1, a3
#pragma unroll
            for (int nt = 0; nt < 2; nt++) {
                uint2 bh = *(const uint2*)&Bh[cur][nt * 8 + g][o];
                uint2 bl = *(const uint2*)&Bl[cur][nt * 8 + g][o];
                mma_bf16(acc[nt][0], acc[nt][1], acc[nt][2], acc[nt][3],
                         aA.x, aB.x, aA.y, aB.y, bh.x, bh.y);
                mma_bf16(acc[nt][0], acc[nt][1], acc[nt][2], acc[nt][3],
                         aA.x, aB.x, aA.y, aB.y, bl.x, bl.y);
            }
        }
        __syncthreads();
    }

    // epilogue: c0:(r0, 2tg) c1:(r0, 2tg+1) c2:(r0+8, 2tg) c3:(r0+8, 2tg+1)
#pragma unroll
    for (int nt = 0; nt < 2; nt++) {
#pragma unroll
        for (int cc = 0; cc < 2; cc++) {          // column sub-index
            const int r   = 2 * tg + cc;          // 0..7 within n8 tile
            const int col = n0 + nt * 8 + r;
            float bv = bias ? bias[col] : 0.f;
            float v0 = acc[nt][cc]     + bv;      // row r0
            float v1 = acc[nt][cc + 2] + bv;      // row r0+8
            if (relu) { v0 = fmaxf(v0, 0.f); v1 = fmaxf(v1, 0.f); }
            if (packOut) {
                const int pcol = n0 + nt * 8 + (((r & 3) << 1) | ((r >> 2) & 1));
                ((U32*)C)[(size_t)(m0 + r0)     * N + pcol] = packA(v0);
                ((U32*)C)[(size_t)(m0 + r0 + 8) * N + pcol] = packA(v1);
            } else {
                ((float*)C)[(size_t)(m0 + r0)     * N + col] = v0;
                ((float*)C)[(size_t)(m0 + r0 + 8) * N + col] = v1;
            }
        }
    }
}

// ---------------------------------------------------------------------------
// pair_mma: out[b,i,n,j] = sum_h relu(s2[b,i,h] + t2[b,j,h]) * fc3[n,h]
// tf32 m16n8k8; pair fragments built in registers, never materialized.
// (unchanged from R6: permuted h layout, all fragment loads are LDS.64)
// ---------------------------------------------------------------------------
#define PROW 264
#define PROW2 132
#define SM_T2F 0
#define SM_WF  (32 * PROW)
#define SM_SF  (64 * PROW)
#define PAIR_SMEM (80 * PROW * 4)

__global__ __launch_bounds__(256, 2) void pair_mma(
    const float* __restrict__ s2, const float* __restrict__ t2,
    const float* __restrict__ fc3, float* __restrict__ out)
{
    extern __shared__ float sm[];
    const int jt = blockIdx.x;
    const int ig = blockIdx.y;
    const int b  = blockIdx.z;

    const int tid  = threadIdx.x;
    const int w    = tid >> 5;
    const int lane = tid & 31;
    const int g    = lane >> 2;
    const int tg   = lane & 3;
    const int wj   = w & 1;
    const int wi   = w >> 1;

    {   // t2 tile: 32 rows x 256 h, permuted
        const float* t2g = t2 + (size_t)(b * 256 + jt * 32) * 256;
#pragma unroll
        for (int r = 0; r < 8; r++) {
            int q   = tid + r * 256;
            int row = q >> 6;
            int c4  = (q & 63) * 4;
            float4 v = *(const float4*)(t2g + row * 256 + c4);
            int base = c4 & ~7;
            int odd  = (c4 >> 2) & 1;
            float* d = sm + SM_T2F + row * PROW + base + odd;
            d[0] = v.x; d[2] = v.y; d[4] = v.z; d[6] = v.w;
        }
    }
    for (int q = tid; q < 32 * 256; q += 256) {
        int n = q >> 8;
        int h = q & 255;
        float v = (n < 25) ? fc3[n * 256 + h] : 0.f;
        int pos = (h & ~7) + ((h & 3) * 2) + ((h >> 2) & 1);
        sm[SM_WF + n * PROW + pos] = __uint_as_float(tf32r(v));
    }
    {
        const float* s2g = s2 + (size_t)(b * 256 + ig * 16) * 256;
        for (int q = tid; q < 16 * 256; q += 256) {
            int row = q >> 8;
            int h = q & 255;
            int pos = (h & ~7) + ((h & 3) * 2) + ((h >> 2) & 1);
            sm[SM_SF + row * PROW + pos] = s2g[row * 256 + h];
        }
    }
    __syncthreads();

    const float2* tA2 = (const float2*)sm + (size_t)(wj * 16 + g) * PROW2 + tg;
    const float2* tW2 = (const float2*)sm + (SM_WF / 2) + (size_t)g * PROW2 + tg;
    const float2* tS2 = (const float2*)sm + (SM_SF / 2) + (size_t)(wi * 4) * PROW2 + tg;

    float acc[4][4][4];
#pragma unroll
    for (int i = 0; i < 4; i++)
#pragma unroll
        for (int nt = 0; nt < 4; nt++)
#pragma unroll
            for (int c = 0; c < 4; c++) acc[i][nt][c] = 0.f;

#pragma unroll 4
    for (int ks = 0; ks < 32; ks++) {
        const int o = ks * 4;
        float2 u0 = tA2[o];
        float2 u1 = tA2[o + 8 * PROW2];
        float2 wv[4];
#pragma unroll
        for (int nt = 0; nt < 4; nt++) wv[nt] = tW2[o + nt * 8 * PROW2];
#pragma unroll
        for (int i = 0; i < 4; i++) {
            float2 sv = tS2[o + i * PROW2];
            U32 a0 = tf32r(fmaxf(u0.x + sv.x, 0.f));
            U32 a1 = tf32r(fmaxf(u1.x + sv.x, 0.f));
            U32 a2 = tf32r(fmaxf(u0.y + sv.y, 0.f));
            U32 a3 = tf32r(fmaxf(u1.y + sv.y, 0.f));
#pragma unroll
            for (int nt = 0; nt < 4; nt++) {
                mma_tf32(acc[i][nt][0], acc[i][nt][1], acc[i][nt][2], acc[i][nt][3],
                         a0, a1, a2, a3,
                         __float_as_uint(wv[nt].x), __float_as_uint(wv[nt].y));
            }
        }
    }

    const int jg = jt * 32 + wj * 16 + g;
#pragma unroll
    for (int i = 0; i < 4; i++) {
        const int ii = ig * 16 + wi * 4 + i;
        float* obase = out + ((size_t)(b * 256 + ii) * 25) * 256 + jg;
#pragma unroll
        for (int nt = 0; nt < 4; nt++) {
            int n0 = nt * 8 + tg * 2;
            if (n0 < 25) {
                obase[(size_t)n0 * 256]     = acc[i][nt][0];
                obase[(size_t)n0 * 256 + 8] = acc[i][nt][2];
            }
            if (n0 + 1 < 25) {
                obase[(size_t)(n0 + 1) * 256]     = acc[i][nt][1];
                obase[(size_t)(n0 + 1) * 256 + 8] = acc[i][nt][3];
            }
        }
    }
}

// ---------------------------------------------------------------------------
// Inputs (metadata order):
// 0 input_tensor [4,256,768]  1 s_fc_w [256,768]  2 s_fc_b [256]
// 3 t_fc_w [256,768]          4 t_fc_b [256]      5 fc2_w [256,512]
// 6 fc2_b [256]               7 fc3_w [25,256]
// Output: float32 [4,256,25,256]
// ---------------------------------------------------------------------------
extern "C" void kernel_launch(void* const* d_in, const int* in_sizes, int n_in,
                              void* d_out, int out_size)
{
    const float* X  = (const float*)d_in[0];
    const float* sw = (const float*)d_in[1];
    const float* sb = (const float*)d_in[2];
    const float* tw = (const float*)d_in[3];
    const float* tb = (const float*)d_in[4];
    const float* w2 = (const float*)d_in[5];
    const float* b2 = (const float*)d_in[6];
    const float* w3 = (const float*)d_in[7];
    float* out = (float*)d_out;

    U32 *xp, *swh, *swl, *twh, *twl, *w2h, *w2l, *gs, *gt;
    float *gs2, *gt2;
    cudaGetSymbolAddress((void**)&xp,  g_xp);
    cudaGetSymbolAddress((void**)&swh, g_swh);
    cudaGetSymbolAddress((void**)&swl, g_swl);
    cudaGetSymbolAddress((void**)&twh, g_twh);
    cudaGetSymbolAddress((void**)&twl, g_twl);
    cudaGetSymbolAddress((void**)&w2h, g_w2h);
    cudaGetSymbolAddress((void**)&w2l, g_w2l);
    cudaGetSymbolAddress((void**)&gs,  g_s);
    cudaGetSymbolAddress((void**)&gt,  g_t);
    cudaGetSymbolAddress((void**)&gs2, g_s2);
    cudaGetSymbolAddress((void**)&gt2, g_t2);

    cudaFuncSetAttribute(pair_mma, cudaFuncAttributeMaxDynamicSharedMemorySize,
                         PAIR_SMEM);

    // one-time split/permute of X and weights
    prep<<<(NX + 255) / 256, 256>>>(X, sw, tw, w2);

    dim3 blk(64);
    dim3 g1(256 / 16, 1024 / 32, 2);   // 16 x 32 x 2 = 1024 CTAs
    // s = relu(X @ s_fc_w^T + s_fc_b), t = relu(X @ t_fc_w^T + t_fc_b)
    // outputs written packed-split + permuted (feed gemm2 as A)
    gemm_bf<<<g1, blk>>>(xp, xp, swh, twh, swl, twl, sb, tb,
                         gs, gt, 768, 768, 256, 1, 1);
    // s2 = s @ w_s^T ; t2 = t @ w_t^T + fc2_b   (fp32 out for pair)
    gemm_bf<<<g1, blk>>>(gs, gt, w2h, w2h + 256, w2l, w2l + 256, nullptr, b2,
                         gs2, gt2, 256, 512, 256, 0, 0);

    dim3 g3(8, 16, 4);                 // 512 CTAs, 256 threads
    pair_mma<<<g3, dim3(256), PAIR_SMEM>>>(gs2, gt2, w3, out);
}

// round 8
// speedup vs baseline: 1.1430x; 1.0651x over previous
#include <cuda_runtime.h>
#include <cuda_bf16.h>

typedef unsigned int U32;

__device__ __forceinline__ U32 tf32r(float x) {
    U32 r;
    asm("cvt.rna.tf32.f32 %0, %1;" : "=r"(r) : "f"(x));
    return r;
}
__device__ __forceinline__ void mma_tf32(
    float& c0, float& c1, float& c2, float& c3,
    U32 a0, U32 a1, U32 a2, U32 a3, U32 b0, U32 b1)
{
    asm volatile(
        "mma.sync.aligned.m16n8k8.row.col.f32.tf32.tf32.f32 "
        "{%0,%1,%2,%3}, {%4,%5,%6,%7}, {%8,%9}, {%0,%1,%2,%3};"
        : "+f"(c0), "+f"(c1), "+f"(c2), "+f"(c3)
        : "r"(a0), "r"(a1), "r"(a2), "r"(a3), "r"(b0), "r"(b1));
}
__device__ __forceinline__ void mma_bf16(
    float& c0, float& c1, float& c2, float& c3,
    U32 a0, U32 a1, U32 a2, U32 a3, U32 b0, U32 b1)
{
    asm volatile(
        "mma.sync.aligned.m16n8k16.row.col.f32.bf16.bf16.f32 "
        "{%0,%1,%2,%3}, {%4,%5,%6,%7}, {%8,%9}, {%0,%1,%2,%3};"
        : "+f"(c0), "+f"(c1), "+f"(c2), "+f"(c3)
        : "r"(a0), "r"(a1), "r"(a2), "r"(a3), "r"(b0), "r"(b1));
}
__device__ __forceinline__ void cp16(U32 dst, const void* src) {
    asm volatile("cp.async.ca.shared.global [%0], [%1], 16;" :: "r"(dst), "l"(src));
}
__device__ __forceinline__ void cp_commit() { asm volatile("cp.async.commit_group;"); }
__device__ __forceinline__ void cp_wait1()  { asm volatile("cp.async.wait_group 1;"); }
__device__ __forceinline__ void cp_wait0()  { asm volatile("cp.async.wait_group 0;"); }

// bf16 hi/lo split. a = hi + lo + r, |r| <= 2^-18 |a|
__device__ __forceinline__ void bsplit(float v, unsigned short& hs, unsigned short& ls) {
    __nv_bfloat16 h = __float2bfloat16_rn(v);
    float hf = __bfloat162float(h);
    __nv_bfloat16 l = __float2bfloat16_rn(v - hf);
    hs = __bfloat16_as_ushort(h);
    ls = __bfloat16_as_ushort(l);
}
__device__ __forceinline__ U32 packA(float v) {
    unsigned short hs, ls; bsplit(v, hs, ls);
    return (U32)hs | ((U32)ls << 16);
}
__device__ __forceinline__ int permk(int k) {
    return (k & ~7) | ((k & 3) << 1) | ((k >> 2) & 1);
}

// Scratch (cudaMalloc forbidden; __device__ globals allowed)
__device__ U32   g_xp [1024 * 768];
__device__ U32   g_swh[256 * 768], g_swl[256 * 768];
__device__ U32   g_twh[256 * 768], g_twl[256 * 768];
__device__ U32   g_w2h[256 * 512], g_w2l[256 * 512];
__device__ U32   g_s  [1024 * 256];
__device__ U32   g_t  [1024 * 256];
__device__ float g_s2 [1024 * 256];
__device__ float g_t2 [1024 * 256];

#define NX  (1024 * 768)
#define NW  (256 * 768)
#define NW2 (256 * 512)

__global__ void prep(const float* __restrict__ X,
                     const float* __restrict__ sw, const float* __restrict__ tw,
                     const float* __restrict__ w2)
{
    int i = blockIdx.x * blockDim.x + threadIdx.x;
    if (i < NX) {
        int row = i / 768, k = i % 768;
        g_xp[row * 768 + permk(k)] = packA(X[i]);
    }
    if (i < NW) {
        int row = i / 768, k = i % 768;
        int o = row * 768 + permk(k);
        unsigned short hs, ls;
        bsplit(sw[i], hs, ls);
        g_swh[o] = (U32)hs | ((U32)hs << 16);
        g_swl[o] = (U32)ls;
        bsplit(tw[i], hs, ls);
        g_twh[o] = (U32)hs | ((U32)hs << 16);
        g_twl[o] = (U32)ls;
    }
    if (i < NW2) {
        int row = i / 512, k = i % 512;
        int o = row * 512 + permk(k);
        unsigned short hs, ls;
        bsplit(w2[i], hs, ls);
        g_w2h[o] = (U32)hs | ((U32)hs << 16);
        g_w2l[o] = (U32)ls;
    }
}

// ---------------------------------------------------------------------------
// gemm_bf v2: C[m][n] = act( sum_k A[m][k]*B[n][k] + bias[n] ), fp32-accurate
// via packed bf16-split (D += A x Bhh + A x Bl0, m16n8k16). Pure LDS+MMA
// mainloop. CTA 32m x 32n, 128 threads (4 warps: (w&1)=m-half, (w>>1)=n-half).
// K-chunk 32 words, cp.async double buffer. 512 CTAs.
// ---------------------------------------------------------------------------
#define SKW 40

__global__ __launch_bounds__(128) void gemm_bf(
    const U32* __restrict__ A0,  const U32* __restrict__ A1,
    const U32* __restrict__ Bh0, const U32* __restrict__ Bh1,
    const U32* __restrict__ Bl0, const U32* __restrict__ Bl1,
    const float* __restrict__ bias0, const float* __restrict__ bias1,
    void* C0, void* C1,
    int K, int ldb, int N, int relu, int packOut)
{
    const U32* A      = blockIdx.z ? A1 : A0;
    const U32* Bhp    = blockIdx.z ? Bh1 : Bh0;
    const U32* Blp    = blockIdx.z ? Bl1 : Bl0;
    const float* bias = blockIdx.z ? bias1 : bias0;
    void* C           = blockIdx.z ? C1 : C0;

    const int m0 = blockIdx.y * 32;
    const int n0 = blockIdx.x * 32;

    __shared__ __align__(16) U32 As[2][32][SKW];
    __shared__ __align__(16) U32 Bh[2][32][SKW];
    __shared__ __align__(16) U32 Bl[2][32][SKW];

    const int tid  = threadIdx.x;
    const int w    = tid >> 5;
    const int lane = tid & 31;
    const int g    = lane >> 2;
    const int tg   = lane & 3;
    const int r0   = (w & 1) * 16 + g;     // m rows r0, r0+8
    const int nb   = (w >> 1) * 16;        // n base for this warp

    const U32 asB = (U32)__cvta_generic_to_shared(&As[0][0][0]);
    const U32 bhB = (U32)__cvta_generic_to_shared(&Bh[0][0][0]);
    const U32 blB = (U32)__cvta_generic_to_shared(&Bl[0][0][0]);
    const U32 buf = 32 * SKW * 4;

    // loaders (128 threads): row = tid>>2 (0..31), words (tid&3)*8 .. +7
    const int lrow = tid >> 2;
    const int lk   = (tid & 3) * 8;

    const U32* Aptr  = A   + (size_t)(m0 + lrow) * K   + lk;
    const U32* Bhptr = Bhp + (size_t)(n0 + lrow) * ldb + lk;
    const U32* Blptr = Blp + (size_t)(n0 + lrow) * ldb + lk;

    const int KC = K / 32;

    float acc[2][4];
#pragma unroll
    for (int nt = 0; nt < 2; nt++)
#pragma unroll
        for (int c = 0; c < 4; c++) acc[nt][c] = 0.f;

    {   // stage chunk 0
#pragma unroll
        for (int c = 0; c < 2; c++) {
            cp16(asB + (lrow * SKW + lk + c * 4) * 4, Aptr  + c * 4);
            cp16(bhB + (lrow * SKW + lk + c * 4) * 4, Bhptr + c * 4);
            cp16(blB + (lrow * SKW + lk + c * 4) * 4, Blptr + c * 4);
        }
        cp_commit();
    }

    for (int kc = 0; kc < KC; kc++) {
        const int cur = kc & 1;
        if (kc + 1 < KC) {
            const int nxt = cur ^ 1;
            const int ko = (kc + 1) * 32;
#pragma unroll
            for (int c = 0; c < 2; c++) {
                cp16(asB + nxt * buf + (lrow * SKW + lk + c * 4) * 4, Aptr  + ko + c * 4);
                cp16(bhB + nxt * buf + (lrow * SKW + lk + c * 4) * 4, Bhptr + ko + c * 4);
                cp16(blB + nxt * buf + (lrow * SKW + lk + c * 4) * 4, Blptr + ko + c * 4);
            }
            cp_commit();
            cp_wait1();
        } else {
            cp_wait0();
        }
        __syncthreads();

#pragma unroll
        for (int ks = 0; ks < 4; ks++) {
            const int o = ks * 8 + 2 * tg;
            uint2 aA = *(const uint2*)&As[cur][r0    ][o];
            uint2 aB = *(const uint2*)&As[cur][r0 + 8][o];
#pragma unroll
            for (int nt = 0; nt < 2; nt++) {
                uint2 bh = *(const uint2*)&Bh[cur][nb + nt * 8 + g][o];
                uint2 bl = *(const uint2*)&Bl[cur][nb + nt * 8 + g][o];
                mma_bf16(acc[nt][0], acc[nt][1], acc[nt][2], acc[nt][3],
                         aA.x, aB.x, aA.y, aB.y, bh.x, bh.y);
                mma_bf16(acc[nt][0], acc[nt][1], acc[nt][2], acc[nt][3],
                         aA.x, aB.x, aA.y, aB.y, bl.x, bl.y);
            }
        }
        __syncthreads();
    }

#pragma unroll
    for (int nt = 0; nt < 2; nt++) {
#pragma unroll
        for (int cc = 0; cc < 2; cc++) {
            const int r   = 2 * tg + cc;
            const int col = n0 + nb + nt * 8 + r;
            float bv = bias ? bias[col] : 0.f;
            float v0 = acc[nt][cc]     + bv;
            float v1 = acc[nt][cc + 2] + bv;
            if (relu) { v0 = fmaxf(v0, 0.f); v1 = fmaxf(v1, 0.f); }
            if (packOut) {
                const int pcol = n0 + nb + nt * 8 + (((r & 3) << 1) | ((r >> 2) & 1));
                ((U32*)C)[(size_t)(m0 + r0)     * N + pcol] = packA(v0);
                ((U32*)C)[(size_t)(m0 + r0 + 8) * N + pcol] = packA(v1);
            } else {
                ((float*)C)[(size_t)(m0 + r0)     * N + col] = v0;
                ((float*)C)[(size_t)(m0 + r0 + 8) * N + col] = v1;
            }
        }
    }
}

// ---------------------------------------------------------------------------
// pair_mma v3: out[b,i,n,j] = sum_h relu(s2[b,i,h] + t2[b,j,h]) * fc3[n,h]
// tf32 m16n8k8; pair fragments built in registers, never materialized.
// Occupancy fix vs R7: smem 84.5->75.3 KB (W stores only 25 real rows; the
// nt=3 fragment's rows 25..31 alias the s region -> garbage feeds only the
// discarded n>=25 columns) and regs capped via launch_bounds(256,3) with a
// two-pass i-loop (acc 32 regs live). -> 3 CTAs/SM, 6 warps/SMSP.
// ---------------------------------------------------------------------------
#define PROW 264
#define PROW2 132
#define SM_T2F 0
#define SM_WF  (32 * PROW)        // 25 rows stored
#define SM_SF  (57 * PROW)        // 16 rows
#define PAIR_SMEM (73 * PROW * 4) // 77088 B -> 3 CTAs/SM

__global__ __launch_bounds__(256, 3) void pair_mma(
    const float* __restrict__ s2, const float* __restrict__ t2,
    const float* __restrict__ fc3, float* __restrict__ out)
{
    extern __shared__ float sm[];
    const int jt = blockIdx.x;   // 0..7  (j tile of 32)
    const int ig = blockIdx.y;   // 0..15 (i group of 16)
    const int b  = blockIdx.z;   // 0..3

    const int tid  = threadIdx.x;
    const int w    = tid >> 5;
    const int lane = tid & 31;
    const int g    = lane >> 2;
    const int tg   = lane & 3;
    const int wj   = w & 1;
    const int wi   = w >> 1;

    {   // t2 tile: 32 rows x 256 h, permuted (h,h+4 adjacent)
        const float* t2g = t2 + (size_t)(b * 256 + jt * 32) * 256;
#pragma unroll
        for (int r = 0; r < 8; r++) {
            int q   = tid + r * 256;
            int row = q >> 6;
            int c4  = (q & 63) * 4;
            float4 v = *(const float4*)(t2g + row * 256 + c4);
            int base = c4 & ~7;
            int odd  = (c4 >> 2) & 1;
            float* d = sm + SM_T2F + row * PROW + base + odd;
            d[0] = v.x; d[2] = v.y; d[4] = v.z; d[6] = v.w;
        }
    }
    // fc3 -> tf32 bits, permuted; ONLY the 25 real rows
    for (int q = tid; q < 25 * 256; q += 256) {
        int n = q >> 8;
        int h = q & 255;
        int pos = (h & ~7) + ((h & 3) * 2) + ((h >> 2) & 1);
        sm[SM_WF + n * PROW + pos] = __uint_as_float(tf32r(fc3[n * 256 + h]));
    }
    {   // s2 rows for this i-group (16 rows), permuted
        const float* s2g = s2 + (size_t)(b * 256 + ig * 16) * 256;
        for (int q = tid; q < 16 * 256; q += 256) {
            int row = q >> 8;
            int h = q & 255;
            int pos = (h & ~7) + ((h & 3) * 2) + ((h >> 2) & 1);
            sm[SM_SF + row * PROW + pos] = s2g[row * 256 + h];
        }
    }
    __syncthreads();

    const float2* tA2 = (const float2*)sm + (size_t)(wj * 16 + g) * PROW2 + tg;
    const float2* tW2 = (const float2*)sm + (SM_WF / 2) + (size_t)g * PROW2 + tg;
    const float2* tS2 = (const float2*)sm + (SM_SF / 2) + (size_t)(wi * 4) * PROW2 + tg;

    const int jg = jt * 32 + wj * 16 + g;

    for (int p = 0; p < 2; p++) {          // two-pass i: acc stays 32 regs
        float acc[2][4][4];
#pragma unroll
        for (int i = 0; i < 2; i++)
#pragma unroll
            for (int nt = 0; nt < 4; nt++)
#pragma unroll
                for (int c = 0; c < 4; c++) acc[i][nt][c] = 0.f;

        const float2* tSp = tS2 + (size_t)(p * 2) * PROW2;

#pragma unroll 4
        for (int ks = 0; ks < 32; ks++) {
            const int o = ks * 4;
            float2 u0 = tA2[o];
            float2 u1 = tA2[o + 8 * PROW2];
            float2 wv[4];
#pragma unroll
            for (int nt = 0; nt < 4; nt++) wv[nt] = tW2[o + nt * 8 * PROW2];
#pragma unroll
            for (int i = 0; i < 2; i++) {
                float2 sv = tSp[o + i * PROW2];
                U32 a0 = tf32r(fmaxf(u0.x + sv.x, 0.f));
                U32 a1 = tf32r(fmaxf(u1.x + sv.x, 0.f));
                U32 a2 = tf32r(fmaxf(u0.y + sv.y, 0.f));
                U32 a3 = tf32r(fmaxf(u1.y + sv.y, 0.f));
#pragma unroll
                for (int nt = 0; nt < 4; nt++) {
                    mma_tf32(acc[i][nt][0], acc[i][nt][1], acc[i][nt][2], acc[i][nt][3],
                             a0, a1, a2, a3,
                             __float_as_uint(wv[nt].x), __float_as_uint(wv[nt].y));
                }
            }
        }

#pragma unroll
        for (int i = 0; i < 2; i++) {
            const int ii = ig * 16 + wi * 4 + p * 2 + i;
            float* obase = out + ((size_t)(b * 256 + ii) * 25) * 256 + jg;
#pragma unroll
            for (int nt = 0; nt < 4; nt++) {
                int n0 = nt * 8 + tg * 2;
                if (n0 < 25) {
                    obase[(size_t)n0 * 256]     = acc[i][nt][0];
                    obase[(size_t)n0 * 256 + 8] = acc[i][nt][2];
                }
                if (n0 + 1 < 25) {
                    obase[(size_t)(n0 + 1) * 256]     = acc[i][nt][1];
                    obase[(size_t)(n0 + 1) * 256 + 8] = acc[i][nt][3];
                }
            }
        }
    }
}

// ---------------------------------------------------------------------------
// Inputs (metadata order):
// 0 input_tensor [4,256,768]  1 s_fc_w [256,768]  2 s_fc_b [256]
// 3 t_fc_w [256,768]          4 t_fc_b [256]      5 fc2_w [256,512]
// 6 fc2_b [256]               7 fc3_w [25,256]
// Output: float32 [4,256,25,256]
// ---------------------------------------------------------------------------
extern "C" void kernel_launch(void* const* d_in, const int* in_sizes, int n_in,
                              void* d_out, int out_size)
{
    const float* X  = (const float*)d_in[0];
    const float* sw = (const float*)d_in[1];
    const float* sb = (const float*)d_in[2];
    const float* tw = (const float*)d_in[3];
    const float* tb = (const float*)d_in[4];
    const float* w2 = (const float*)d_in[5];
    const float* b2 = (const float*)d_in[6];
    const float* w3 = (const float*)d_in[7];
    float* out = (float*)d_out;

    U32 *xp, *swh, *swl, *twh, *twl, *w2h, *w2l, *gs, *gt;
    float *gs2, *gt2;
    cudaGetSymbolAddress((void**)&xp,  g_xp);
    cudaGetSymbolAddress((void**)&swh, g_swh);
    cudaGetSymbolAddress((void**)&swl, g_swl);
    cudaGetSymbolAddress((void**)&twh, g_twh);
    cudaGetSymbolAddress((void**)&twl, g_twl);
    cudaGetSymbolAddress((void**)&w2h, g_w2h);
    cudaGetSymbolAddress((void**)&w2l, g_w2l);
    cudaGetSymbolAddress((void**)&gs,  g_s);
    cudaGetSymbolAddress((void**)&gt,  g_t);
    cudaGetSymbolAddress((void**)&gs2, g_s2);
    cudaGetSymbolAddress((void**)&gt2, g_t2);

    cudaFuncSetAttribute(pair_mma, cudaFuncAttributeMaxDynamicSharedMemorySize,
                         PAIR_SMEM);

    prep<<<(NX + 255) / 256, 256>>>(X, sw, tw, w2);

    dim3 blk(128);
    dim3 g1(256 / 32, 1024 / 32, 2);   // 8 x 32 x 2 = 512 CTAs
    gemm_bf<<<g1, blk>>>(xp, xp, swh, twh, swl, twl, sb, tb,
                         gs, gt, 768, 768, 256, 1, 1);
    gemm_bf<<<g1, blk>>>(gs, gt, w2h, w2h + 256, w2l, w2l + 256, nullptr, b2,
                         gs2, gt2, 256, 512, 256, 0, 0);

    dim3 g3(8, 16, 4);                 // 512 CTAs, 256 threads
    pair_mma<<<g3, dim3(256), PAIR_SMEM>>>(gs2, gt2, w3, out);
}

// round 10
// speedup vs baseline: 1.2942x; 1.1323x over previous
#include <cuda_runtime.h>
#include <cuda_bf16.h>

typedef unsigned int U32;

__device__ __forceinline__ U32 tf32r(float x) {
    U32 r;
    asm("cvt.rna.tf32.f32 %0, %1;" : "=r"(r) : "f"(x));
    return r;
}
__device__ __forceinline__ void mma_tf32(
    float& c0, float& c1, float& c2, float& c3,
    U32 a0, U32 a1, U32 a2, U32 a3, U32 b0, U32 b1)
{
    asm volatile(
        "mma.sync.aligned.m16n8k8.row.col.f32.tf32.tf32.f32 "
        "{%0,%1,%2,%3}, {%4,%5,%6,%7}, {%8,%9}, {%0,%1,%2,%3};"
        : "+f"(c0), "+f"(c1), "+f"(c2), "+f"(c3)
        : "r"(a0), "r"(a1), "r"(a2), "r"(a3), "r"(b0), "r"(b1));
}
__device__ __forceinline__ void mma_bf16(
    float& c0, float& c1, float& c2, float& c3,
    U32 a0, U32 a1, U32 a2, U32 a3, U32 b0, U32 b1)
{
    asm volatile(
        "mma.sync.aligned.m16n8k16.row.col.f32.bf16.bf16.f32 "
        "{%0,%1,%2,%3}, {%4,%5,%6,%7}, {%8,%9}, {%0,%1,%2,%3};"
        : "+f"(c0), "+f"(c1), "+f"(c2), "+f"(c3)
        : "r"(a0), "r"(a1), "r"(a2), "r"(a3), "r"(b0), "r"(b1));
}
__device__ __forceinline__ void cp16(U32 dst, const void* src) {
    asm volatile("cp.async.ca.shared.global [%0], [%1], 16;" :: "r"(dst), "l"(src));
}
__device__ __forceinline__ void cp_commit() { asm volatile("cp.async.commit_group;"); }
__device__ __forceinline__ void cp_wait1()  { asm volatile("cp.async.wait_group 1;"); }
__device__ __forceinline__ void cp_wait0()  { asm volatile("cp.async.wait_group 0;"); }

// bf16 hi/lo split. a = hi + lo + r, |r| <= 2^-18 |a|
__device__ __forceinline__ void bsplit(float v, unsigned short& hs, unsigned short& ls) {
    __nv_bfloat16 h = __float2bfloat16_rn(v);
    float hf = __bfloat162float(h);
    __nv_bfloat16 l = __float2bfloat16_rn(v - hf);
    hs = __bfloat16_as_ushort(h);
    ls = __bfloat16_as_ushort(l);
}
__device__ __forceinline__ U32 packA(float v) {
    unsigned short hs, ls; bsplit(v, hs, ls);
    return (U32)hs | ((U32)ls << 16);
}
// permute k within its 8-group so fragment LDS.64 gets (k, k+4) adjacent
__device__ __forceinline__ int permk(int k) {
    return (k & ~7) | ((k & 3) << 1) | ((k >> 2) & 1);
}

// Scratch (cudaMalloc forbidden; __device__ globals allowed)
__device__ U32   g_xp [1024 * 768];
__device__ U32   g_swh[256 * 768], g_swl[256 * 768];
__device__ U32   g_twh[256 * 768], g_twl[256 * 768];
__device__ U32   g_w2h[256 * 512], g_w2l[256 * 512];
__device__ U32   g_w3p[25 * 256];                 // fc3 tf32 bits, k-permuted
__device__ U32   g_s  [1024 * 256];               // stage1 out, packed-split, permuted
__device__ U32   g_t  [1024 * 256];
__device__ float g_s2 [1024 * 256];               // stage2 out, fp32, h-permuted
__device__ float g_t2 [1024 * 256];

#define NX  (1024 * 768)
#define NW  (256 * 768)
#define NW2 (256 * 512)
#define NW3 (25 * 256)

__global__ void prep(const float* __restrict__ X,
                     const float* __restrict__ sw, const float* __restrict__ tw,
                     const float* __restrict__ w2, const float* __restrict__ w3)
{
    int i = blockIdx.x * blockDim.x + threadIdx.x;
    if (i < NX) {
        int row = i / 768, k = i % 768;
        g_xp[row * 768 + permk(k)] = packA(X[i]);
    }
    if (i < NW) {
        int row = i / 768, k = i % 768;
        int o = row * 768 + permk(k);
        unsigned short hs, ls;
        bsplit(sw[i], hs, ls);
        g_swh[o] = (U32)hs | ((U32)hs << 16);
        g_swl[o] = (U32)ls;
        bsplit(tw[i], hs, ls);
        g_twh[o] = (U32)hs | ((U32)hs << 16);
        g_twl[o] = (U32)ls;
    }
    if (i < NW2) {
        int row = i / 512, k = i % 512;
        int o = row * 512 + permk(k);
        unsigned short hs, ls;
        bsplit(w2[i], hs, ls);
        g_w2h[o] = (U32)hs | ((U32)hs << 16);
        g_w2l[o] = (U32)ls;
    }
    if (i < NW3) {
        int row = i / 256, k = i % 256;
        g_w3p[row * 256 + permk(k)] = tf32r(w3[i]);
    }
}

// ---------------------------------------------------------------------------
// gemm_bf: C[m][n] = act( sum_k A[m][k]*B[n][k] + bias[n] ), fp32-accurate
// via packed bf16-split (D += A x Bhh + A x Bl0, m16n8k16). Pure LDS+MMA
// mainloop. CTA 32m x 32n, 128 threads. cp.async double buffer. 512 CTAs.
// packOut: 0 = plain fp32, 1 = packed-split U32 (permuted), 2 = fp32 permuted.
// ---------------------------------------------------------------------------
#define SKW 40

__global__ __launch_bounds__(128) void gemm_bf(
    const U32* __restrict__ A0,  const U32* __restrict__ A1,
    const U32* __restrict__ Bh0, const U32* __restrict__ Bh1,
    const U32* __restrict__ Bl0, const U32* __restrict__ Bl1,
    const float* __restrict__ bias0, const float* __restrict__ bias1,
    void* C0, void* C1,
    int K, int ldb, int N, int relu, int packOut)
{
    const U32* A      = blockIdx.z ? A1 : A0;
    const U32* Bhp    = blockIdx.z ? Bh1 : Bh0;
    const U32* Blp    = blockIdx.z ? Bl1 : Bl0;
    const float* bias = blockIdx.z ? bias1 : bias0;
    void* C           = blockIdx.z ? C1 : C0;

    const int m0 = blockIdx.y * 32;
    const int n0 = blockIdx.x * 32;

    __shared__ __align__(16) U32 As[2][32][SKW];
    __shared__ __align__(16) U32 Bh[2][32][SKW];
    __shared__ __align__(16) U32 Bl[2][32][SKW];

    const int tid  = threadIdx.x;
    const int w    = tid >> 5;
    const int lane = tid & 31;
    const int g    = lane >> 2;
    const int tg   = lane & 3;
    const int r0   = (w & 1) * 16 + g;
    const int nb   = (w >> 1) * 16;

    const U32 asB = (U32)__cvta_generic_to_shared(&As[0][0][0]);
    const U32 bhB = (U32)__cvta_generic_to_shared(&Bh[0][0][0]);
    const U32 blB = (U32)__cvta_generic_to_shared(&Bl[0][0][0]);
    const U32 buf = 32 * SKW * 4;

    const int lrow = tid >> 2;
    const int lk   = (tid & 3) * 8;

    const U32* Aptr  = A   + (size_t)(m0 + lrow) * K   + lk;
    const U32* Bhptr = Bhp + (size_t)(n0 + lrow) * ldb + lk;
    const U32* Blptr = Blp + (size_t)(n0 + lrow) * ldb + lk;

    const int KC = K / 32;

    float acc[2][4];
#pragma unroll
    for (int nt = 0; nt < 2; nt++)
#pragma unroll
        for (int c = 0; c < 4; c++) acc[nt][c] = 0.f;

    {
#pragma unroll
        for (int c = 0; c < 2; c++) {
            cp16(asB + (lrow * SKW + lk + c * 4) * 4, Aptr  + c * 4);
            cp16(bhB + (lrow * SKW + lk + c * 4) * 4, Bhptr + c * 4);
            cp16(blB + (lrow * SKW + lk + c * 4) * 4, Blptr + c * 4);
        }
        cp_commit();
    }

    for (int kc = 0; kc < KC; kc++) {
        const int cur = kc & 1;
        if (kc + 1 < KC) {
            const int nxt = cur ^ 1;
            const int ko = (kc + 1) * 32;
#pragma unroll
            for (int c = 0; c < 2; c++) {
                cp16(asB + nxt * buf + (lrow * SKW + lk + c * 4) * 4, Aptr  + ko + c * 4);
                cp16(bhB + nxt * buf + (lrow * SKW + lk + c * 4) * 4, Bhptr + ko + c * 4);
                cp16(blB + nxt * buf + (lrow * SKW + lk + c * 4) * 4, Blptr + ko + c * 4);
            }
            cp_commit();
            cp_wait1();
        } else {
            cp_wait0();
        }
        __syncthreads();

#pragma unroll
        for (int ks = 0; ks < 4; ks++) {
            const int o = ks * 8 + 2 * tg;
            uint2 aA = *(const uint2*)&As[cur][r0    ][o];
            uint2 aB = *(const uint2*)&As[cur][r0 + 8][o];
#pragma unroll
            for (int nt = 0; nt < 2; nt++) {
                uint2 bh = *(const uint2*)&Bh[cur][nb + nt * 8 + g][o];
                uint2 bl = *(const uint2*)&Bl[cur][nb + nt * 8 + g][o];
                mma_bf16(acc[nt][0], acc[nt][1], acc[nt][2], acc[nt][3],
                         aA.x, aB.x, aA.y, aB.y, bh.x, bh.y);
                mma_bf16(acc[nt][0], acc[nt][1], acc[nt][2], acc[nt][3],
                         aA.x, aB.x, aA.y, aB.y, bl.x, bl.y);
            }
        }
        __syncthreads();
    }

#pragma unroll
    for (int nt = 0; nt < 2; nt++) {
#pragma unroll
        for (int cc = 0; cc < 2; cc++) {
            const int r   = 2 * tg + cc;
            const int col = n0 + nb + nt * 8 + r;
            float bv = bias ? bias[col] : 0.f;
            float v0 = acc[nt][cc]     + bv;
            float v1 = acc[nt][cc + 2] + bv;
            if (relu) { v0 = fmaxf(v0, 0.f); v1 = fmaxf(v1, 0.f); }
            const int pcol = n0 + nb + nt * 8 + (((r & 3) << 1) | ((r >> 2) & 1));
            if (packOut == 1) {
                ((U32*)C)[(size_t)(m0 + r0)     * N + pcol] = packA(v0);
                ((U32*)C)[(size_t)(m0 + r0 + 8) * N + pcol] = packA(v1);
            } else if (packOut == 2) {
                ((float*)C)[(size_t)(m0 + r0)     * N + pcol] = v0;
                ((float*)C)[(size_t)(m0 + r0 + 8) * N + pcol] = v1;
            } else {
                ((float*)C)[(size_t)(m0 + r0)     * N + col] = v0;
                ((float*)C)[(size_t)(m0 + r0 + 8) * N + col] = v1;
            }
        }
    }
}

// ---------------------------------------------------------------------------
// pair_mma v4: out[b,i,n,j] = sum_h relu(s2[b,i,h] + t2[b,j,h]) * fc3[n,h]
// tf32 m16n8k8; pair fragments built in registers, never materialized.
// smem 68.6 KB (t 32 rows + W 25 rows + s 8 rows) -> TRUE 3 CTAs/SM.
// All inputs pre-permuted in gmem -> staging is pure cp.async.
// Single-pass i (acc 32 regs). 1024 CTAs, launch_bounds(256,3).
// W stores only 25 real rows; nt=3 rows 25..31 alias the s region (finite
// floats) and feed only the discarded n>=25 output columns.
// ---------------------------------------------------------------------------
#define PROW 264
#define PROW2 132
#define SM_T2F 0
#define SM_WF  (32 * PROW)          // W rows 32..56
#define SM_SF  (57 * PROW)          // s rows 57..64
#define PAIR_SMEM (65 * PROW * 4)   // 68640 B

__global__ __launch_bounds__(256, 3) void pair_mma(
    const float* __restrict__ s2, const float* __restrict__ t2,
    const U32* __restrict__ w3p, float* __restrict__ out)
{
    extern __shared__ float sm[];
    const int jt = blockIdx.x;   // 0..7  (j tile of 32)
    const int ig = blockIdx.y;   // 0..31 (i group of 8)
    const int b  = blockIdx.z;   // 0..3

    const int tid  = threadIdx.x;
    const int w    = tid >> 5;
    const int lane = tid & 31;
    const int g    = lane >> 2;
    const int tg   = lane & 3;
    const int wj   = w & 1;       // j half
    const int wi   = w >> 1;      // i pair (0..3)

    const U32 smB = (U32)__cvta_generic_to_shared(sm);

    // ---- staging: pure cp.async (sources already permuted) ----
    {   // t2: 32 rows x 256 floats = 2048 float4
        const float* t2g = t2 + (size_t)(b * 256 + jt * 32) * 256;
#pragma unroll
        for (int r = 0; r < 8; r++) {
            int q   = tid + r * 256;
            int row = q >> 6;
            int c4  = (q & 63) * 4;
            cp16(smB + (SM_T2F + row * PROW + c4) * 4, t2g + row * 256 + c4);
        }
    }
    // fc3 tf32: 25 rows x 256 = 1600 float4
    for (int q = tid; q < 1600; q += 256) {
        int row = q >> 6;
        int c4  = (q & 63) * 4;
        cp16(smB + (SM_WF + row * PROW + c4) * 4, w3p + row * 256 + c4);
    }
    {   // s2: 8 rows x 256 = 512 float4
        const float* s2g = s2 + (size_t)(b * 256 + ig * 8) * 256;
#pragma unroll
        for (int r = 0; r < 2; r++) {
            int q   = tid + r * 256;
            int row = q >> 6;
            int c4  = (q & 63) * 4;
            cp16(smB + (SM_SF + row * PROW + c4) * 4, s2g + row * 256 + c4);
        }
    }
    cp_commit();
    cp_wait0();
    __syncthreads();

    const float2* tA2 = (const float2*)sm + (size_t)(wj * 16 + g) * PROW2 + tg;
    const float2* tW2 = (const float2*)sm + (SM_WF / 2) + (size_t)g * PROW2 + tg;
    const float2* tS2 = (const float2*)sm + (SM_SF / 2) + (size_t)(wi * 2) * PROW2 + tg;

    float acc[2][4][4];   // [i][nt][c]
#pragma unroll
    for (int i = 0; i < 2; i++)
#pragma unroll
        for (int nt = 0; nt < 4; nt++)
#pragma unroll
            for (int c = 0; c < 4; c++) acc[i][nt][c] = 0.f;

#pragma unroll 4
    for (int ks = 0; ks < 32; ks++) {
        const int o = ks * 4;
        float2 u0 = tA2[o];
        float2 u1 = tA2[o + 8 * PROW2];
        float2 wv[4];
#pragma unroll
        for (int nt = 0; nt < 4; nt++) wv[nt] = tW2[o + nt * 8 * PROW2];
#pragma unroll
        for (int i = 0; i < 2; i++) {
            float2 sv = tS2[o + i * PROW2];
            U32 a0 = tf32r(fmaxf(u0.x + sv.x, 0.f));
            U32 a1 = tf32r(fmaxf(u1.x + sv.x, 0.f));
            U32 a2 = tf32r(fmaxf(u0.y + sv.y, 0.f));
            U32 a3 = tf32r(fmaxf(u1.y + sv.y, 0.f));
#pragma unroll
            for (int nt = 0; nt < 4; nt++) {
                mma_tf32(acc[i][nt][0], acc[i][nt][1], acc[i][nt][2], acc[i][nt][3],
                         a0, a1, a2, a3,
                         __float_as_uint(wv[nt].x), __float_as_uint(wv[nt].y));
            }
        }
    }

    const int jg = jt * 32 + wj * 16 + g;
#pragma unroll
    for (int i = 0; i < 2; i++) {
        const int ii = ig * 8 + wi * 2 + i;
        float* obase = out + ((size_t)(b * 256 + ii) * 25) * 256 + jg;
#pragma unroll
        for (int nt = 0; nt < 4; nt++) {
            int n0 = nt * 8 + tg * 2;
            if (n0 < 25) {
                obase[(size_t)n0 * 256]     = acc[i][nt][0];
                obase[(size_t)n0 * 256 + 8] = acc[i][nt][2];
            }
            if (n0 + 1 < 25) {
                obase[(size_t)(n0 + 1) * 256]     = acc[i][nt][1];
                obase[(size_t)(n0 + 1) * 256 + 8] = acc[i][nt][3];
            }
        }
    }
}

// ---------------------------------------------------------------------------
// Inputs (metadata order):
// 0 input_tensor [4,256,768]  1 s_fc_w [256,768]  2 s_fc_b [256]
// 3 t_fc_w [256,768]          4 t_fc_b [256]      5 fc2_w [256,512]
// 6 fc2_b [256]               7 fc3_w [25,256]
// Output: float32 [4,256,25,256]
// ---------------------------------------------------------------------------
extern "C" void kernel_launch(void* const* d_in, const int* in_sizes, int n_in,
                              void* d_out, int out_size)
{
    const float* X  = (const float*)d_in[0];
    const float* sw = (const float*)d_in[1];
    const float* sb = (const float*)d_in[2];
    const float* tw = (const float*)d_in[3];
    const float* tb = (const float*)d_in[4];
    const float* w2 = (const float*)d_in[5];
    const float* b2 = (const float*)d_in[6];
    const float* w3 = (const float*)d_in[7];
    float* out = (float*)d_out;

    U32 *xp, *swh, *swl, *twh, *twl, *w2h, *w2l, *w3p, *gs, *gt;
    float *gs2, *gt2;
    cudaGetSymbolAddress((void**)&xp,  g_xp);
    cudaGetSymbolAddress((void**)&swh, g_swh);
    cudaGetSymbolAddress((void**)&swl, g_swl);
    cudaGetSymbolAddress((void**)&twh, g_twh);
    cudaGetSymbolAddress((void**)&twl, g_twl);
    cudaGetSymbolAddress((void**)&w2h, g_w2h);
    cudaGetSymbolAddress((void**)&w2l, g_w2l);
    cudaGetSymbolAddress((void**)&w3p, g_w3p);
    cudaGetSymbolAddress((void**)&gs,  g_s);
    cudaGetSymbolAddress((void**)&gt,  g_t);
    cudaGetSymbolAddress((void**)&gs2, g_s2);
    cudaGetSymbolAddress((void**)&gt2, g_t2);

    cudaFuncSetAttribute(pair_mma, cudaFuncAttributeMaxDynamicSharedMemorySize,
                         PAIR_SMEM);

    prep<<<(NX + 255) / 256, 256>>>(X, sw, tw, w2, w3);

    dim3 blk(128);
    dim3 g1(256 / 32, 1024 / 32, 2);   // 512 CTAs
    gemm_bf<<<g1, blk>>>(xp, xp, swh, twh, swl, twl, sb, tb,
                         gs, gt, 768, 768, 256, 1, 1);
    // s2/t2 written fp32 with h-permutation (packOut=2) for pair staging
    gemm_bf<<<g1, blk>>>(gs, gt, w2h, w2h + 256, w2l, w2l + 256, nullptr, b2,
                         gs2, gt2, 256, 512, 256, 0, 2);

    dim3 g3(8, 32, 4);                 // 1024 CTAs, 256 threads
    pair_mma<<<g3, dim3(256), PAIR_SMEM>>>(gs2, gt2, w3p, out);
}